// round 5
// baseline (speedup 1.0000x reference)
#include <cuda_runtime.h>
#include <cuda_bf16.h>
#include <cstdint>

// ============================================================================
// SimplifiedTopologyExtractor — algebraic reduction:
//   out = ReLU(LayerNorm(emb[:, :, :256] @ W_enc + b_enc))
// (pooled == embeddings exactly; proj/cdist/topk is dead code.)
//
// fp32 GEMM via bf16 hi/lo split on mma.sync m16n8k16 (tcgen05 needs sm_103a
// PTX target, not emitted by this harness): a*b ≈ ah*bh + ah*bl + al*bh.
// Round 5: conversion hoisted into prep kernels (B was being re-converted by
// all 256 CTAs); GEMM mainloop is pure cp.async (3-stage) + LDSM + HMMA.
// ============================================================================

#define THREADS 256
#define MTILE 64
#define KD 256
#define KCH 16
#define NCHUNK (KD / KCH)
#define STAGES 3

// smem strides/offsets (bytes) — layout identical to proven R3 kernel
#define A_STRIDE 48
#define B_STRIDE 1040
#define OFF_AH 0
#define OFF_AL (64 * A_STRIDE)                  // 3072
#define OFF_BH (2 * 64 * A_STRIDE)              // 6144
#define OFF_BL (OFF_BH + KCH * B_STRIDE)        // 22784
#define STAGE_B (OFF_BL + KCH * B_STRIDE)       // 39424 per stage
#define OFF_PS (STAGES * STAGE_B)               // 118272
#define OFF_PQ (OFF_PS + 2048)
#define OFF_MZ (OFF_PQ + 2048)
#define SMEM_TOTAL (OFF_MZ + 512)               // 122880

// prepped operands (bf16 hi/lo), chunk-shaped for linear cp.async
//   g_Apre: [mtile 256][chunk 16][part 2][r 64][k 16]  (4096 B per (mtile,chunk))
//   g_Bpre: [chunk 16][part 2][kr 16][n 512]           (32768 B per chunk)
__device__ __align__(16) unsigned char g_Apre[256 * 16 * 4096];  // 16 MB
__device__ __align__(16) unsigned char g_Bpre[16 * 32768];       // 512 KB

__device__ __forceinline__ uint32_t smem_u32(const void* p) {
    uint32_t a;
    asm("{ .reg .u64 t; cvta.to.shared.u64 t, %1; cvt.u32.u64 %0, t; }"
        : "=r"(a) : "l"(p));
    return a;
}

__device__ __forceinline__ void cp_async16(uint32_t dst, const void* src) {
    asm volatile("cp.async.cg.shared.global [%0], [%1], 16;\n"
                 :: "r"(dst), "l"(src));
}

__device__ __forceinline__ void ldsm4(uint32_t* r, uint32_t addr) {
    asm volatile("ldmatrix.sync.aligned.m8n8.x4.shared.b16 {%0,%1,%2,%3}, [%4];"
                 : "=r"(r[0]), "=r"(r[1]), "=r"(r[2]), "=r"(r[3]) : "r"(addr));
}
__device__ __forceinline__ void ldsm4t(uint32_t* r, uint32_t addr) {
    asm volatile("ldmatrix.sync.aligned.m8n8.x4.trans.shared.b16 {%0,%1,%2,%3}, [%4];"
                 : "=r"(r[0]), "=r"(r[1]), "=r"(r[2]), "=r"(r[3]) : "r"(addr));
}

__device__ __forceinline__ void mma16816(float* d, const uint32_t* a,
                                         uint32_t b0, uint32_t b1) {
    asm volatile(
        "mma.sync.aligned.m16n8k16.row.col.f32.bf16.bf16.f32 "
        "{%0,%1,%2,%3}, {%4,%5,%6,%7}, {%8,%9}, {%0,%1,%2,%3};"
        : "+f"(d[0]), "+f"(d[1]), "+f"(d[2]), "+f"(d[3])
        : "r"(a[0]), "r"(a[1]), "r"(a[2]), "r"(a[3]), "r"(b0), "r"(b1));
}

__device__ __forceinline__ void split_f4(float4 v, uint32_t& h01, uint32_t& h23,
                                         uint32_t& l01, uint32_t& l23) {
    float f[4] = {v.x, v.y, v.z, v.w};
    unsigned short hs[4], ls[4];
#pragma unroll
    for (int i = 0; i < 4; i++) {
        __nv_bfloat16 h = __float2bfloat16(f[i]);
        float rem = f[i] - __bfloat162float(h);
        __nv_bfloat16 l = __float2bfloat16(rem);
        hs[i] = __bfloat16_as_ushort(h);
        ls[i] = __bfloat16_as_ushort(l);
    }
    h01 = (uint32_t)hs[0] | ((uint32_t)hs[1] << 16);
    h23 = (uint32_t)hs[2] | ((uint32_t)hs[3] << 16);
    l01 = (uint32_t)ls[0] | ((uint32_t)ls[1] << 16);
    l23 = (uint32_t)ls[2] | ((uint32_t)ls[3] << 16);
}

// ---- prep A: emb[:, :256] -> hi/lo bf16, chunk-tiled ----
__global__ void prep_a_kernel(const float* __restrict__ emb) {
    int t = blockIdx.x * 256 + threadIdx.x;   // 16384 * 64
    int row = t >> 6;
    int kq  = t & 63;
    float4 v = *(const float4*)(emb + (size_t)row * 512 + kq * 4);
    uint32_t h01, h23, l01, l23;
    split_f4(v, h01, h23, l01, l23);
    int mtile = row >> 6, r = row & 63, c = kq >> 2, kp = kq & 3;
    size_t base = ((size_t)(mtile * 16 + c)) * 4096 + (size_t)r * 32 + kp * 8;
    *(uint2*)(g_Apre + base)        = make_uint2(h01, h23);
    *(uint2*)(g_Apre + base + 2048) = make_uint2(l01, l23);
}

// ---- prep B: W_enc[256,512] -> hi/lo bf16, chunk-tiled ----
__global__ void prep_b_kernel(const float* __restrict__ W) {
    int t = blockIdx.x * 256 + threadIdx.x;   // 256 * 128
    int k  = t >> 7;
    int nq = t & 127;
    float4 v = *(const float4*)(W + (size_t)k * 512 + nq * 4);
    uint32_t h01, h23, l01, l23;
    split_f4(v, h01, h23, l01, l23);
    int c = k >> 4, kr = k & 15;
    size_t base = (size_t)c * 32768 + (size_t)kr * 1024 + nq * 8;
    *(uint2*)(g_Bpre + base)         = make_uint2(h01, h23);
    *(uint2*)(g_Bpre + base + 16384) = make_uint2(l01, l23);
}

// ---- GEMM + fused bias/LayerNorm/ReLU ----
__global__ void __launch_bounds__(THREADS)
gemm_ln_kernel(const float* __restrict__ bias,
               const float* __restrict__ gamma,
               const float* __restrict__ beta,
               float* __restrict__ out)
{
    extern __shared__ __align__(1024) unsigned char smem[];
    const uint32_t sb = smem_u32(smem);
    const int tid = threadIdx.x;
    const int wid = tid >> 5;
    const int lane = tid & 31;
    const int mtile = blockIdx.x;
    const int m0 = mtile * MTILE;

    float acc[4][8][4];
#pragma unroll
    for (int mt = 0; mt < 4; mt++)
#pragma unroll
        for (int nt = 0; nt < 8; nt++)
#pragma unroll
            for (int e = 0; e < 4; e++) acc[mt][nt][e] = 0.0f;

    // per-thread copy decomposition (fixed across chunks)
    const int a_part = tid >> 7, a_r = (tid >> 1) & 63, a_half = tid & 1;
    const uint32_t a_dst_off = (uint32_t)(a_part ? OFF_AL : OFF_AH)
                             + (uint32_t)a_r * A_STRIDE + (uint32_t)a_half * 16;

    uint32_t b_dst_off[8];
#pragma unroll
    for (int i = 0; i < 8; i++) {
        int g = tid + i * 256;
        int part = g >> 10, kr = (g >> 6) & 15, col = g & 63;
        b_dst_off[i] = (uint32_t)(part ? OFF_BL : OFF_BH)
                     + (uint32_t)kr * B_STRIDE + (uint32_t)col * 16;
    }

#define ISSUE_CHUNK(cc) do {                                                   \
    const int _c = (cc);                                                       \
    const uint32_t _st = sb + (uint32_t)(_c % STAGES) * STAGE_B;               \
    cp_async16(_st + a_dst_off,                                                \
               g_Apre + ((size_t)(mtile * 16 + _c)) * 4096 + (size_t)tid * 16);\
    _Pragma("unroll")                                                          \
    for (int _i = 0; _i < 8; _i++)                                             \
        cp_async16(_st + b_dst_off[_i],                                        \
                   g_Bpre + (size_t)_c * 32768 + (size_t)(tid + _i * 256) * 16);\
    asm volatile("cp.async.commit_group;");                                    \
} while (0)

    // prologue: stages 0,1
    ISSUE_CHUNK(0);
    ISSUE_CHUNK(1);

    // ldmatrix lane addressing
    const uint32_t lrow = lane & 15, lchk = lane >> 4;
    const uint32_t aLane = lrow * A_STRIDE + lchk * 16;
    const uint32_t bLane = lrow * B_STRIDE + lchk * 16 + (uint32_t)wid * 128;

#pragma unroll 1
    for (int c = 0; c < NCHUNK; ++c) {
        if (c < NCHUNK - 2)
            asm volatile("cp.async.wait_group 1;");
        else
            asm volatile("cp.async.wait_group 0;");
        __syncthreads();

        if (c + 2 < NCHUNK) ISSUE_CHUNK(c + 2);

        const uint32_t st = sb + (uint32_t)(c % STAGES) * STAGE_B;

        uint32_t Ah[4][4], Al[4][4];
#pragma unroll
        for (int mt = 0; mt < 4; mt++) {
            ldsm4(Ah[mt], st + OFF_AH + (uint32_t)mt * 16 * A_STRIDE + aLane);
            ldsm4(Al[mt], st + OFF_AL + (uint32_t)mt * 16 * A_STRIDE + aLane);
        }
#pragma unroll
        for (int j = 0; j < 4; j++) {
            uint32_t Bh[4], Bl[4];
            ldsm4t(Bh, st + OFF_BH + (uint32_t)j * 32 + bLane);
            ldsm4t(Bl, st + OFF_BL + (uint32_t)j * 32 + bLane);
#pragma unroll
            for (int mt = 0; mt < 4; mt++) {
#pragma unroll
                for (int nn = 0; nn < 2; nn++) {
                    float* d = acc[mt][j * 2 + nn];
                    mma16816(d, Ah[mt], Bh[nn * 2], Bh[nn * 2 + 1]);
                    mma16816(d, Ah[mt], Bl[nn * 2], Bl[nn * 2 + 1]);
                    mma16816(d, Al[mt], Bh[nn * 2], Bh[nn * 2 + 1]);
                }
            }
        }
    }

    // ======== fused epilogue: +bias, LayerNorm(512), *gamma+beta, ReLU ========
    const int g = lane >> 2, t4 = lane & 3;
    float* ps = (float*)(smem + OFF_PS);      // [64 rows][8 warps]
    float* pq = (float*)(smem + OFF_PQ);
    float2* mz = (float2*)(smem + OFF_MZ);    // [64] {mu, rstd}

    float s[8], q[8];
#pragma unroll
    for (int r8 = 0; r8 < 8; r8++) { s[r8] = 0.f; q[r8] = 0.f; }

#pragma unroll
    for (int mt = 0; mt < 4; mt++) {
#pragma unroll
        for (int nt = 0; nt < 8; nt++) {
            const int col = wid * 64 + nt * 8 + t4 * 2;
            const float2 bv = *(const float2*)(bias + col);
            acc[mt][nt][0] += bv.x; acc[mt][nt][1] += bv.y;
            acc[mt][nt][2] += bv.x; acc[mt][nt][3] += bv.y;
            s[mt * 2 + 0] += acc[mt][nt][0] + acc[mt][nt][1];
            q[mt * 2 + 0] += acc[mt][nt][0] * acc[mt][nt][0]
                           + acc[mt][nt][1] * acc[mt][nt][1];
            s[mt * 2 + 1] += acc[mt][nt][2] + acc[mt][nt][3];
            q[mt * 2 + 1] += acc[mt][nt][2] * acc[mt][nt][2]
                           + acc[mt][nt][3] * acc[mt][nt][3];
        }
    }
#pragma unroll
    for (int r8 = 0; r8 < 8; r8++) {
        s[r8] += __shfl_xor_sync(0xffffffffu, s[r8], 1);
        q[r8] += __shfl_xor_sync(0xffffffffu, q[r8], 1);
        s[r8] += __shfl_xor_sync(0xffffffffu, s[r8], 2);
        q[r8] += __shfl_xor_sync(0xffffffffu, q[r8], 2);
    }
    if (t4 == 0) {
#pragma unroll
        for (int r8 = 0; r8 < 8; r8++) {
            const int row = (r8 >> 1) * 16 + (r8 & 1) * 8 + g;
            ps[row * 8 + wid] = s[r8];
            pq[row * 8 + wid] = q[r8];
        }
    }
    __syncthreads();
    if (tid < 64) {
        float ss = 0.f, qq = 0.f;
#pragma unroll
        for (int w = 0; w < 8; w++) { ss += ps[tid * 8 + w]; qq += pq[tid * 8 + w]; }
        const float mu  = ss * (1.0f / 512.0f);
        const float var = qq * (1.0f / 512.0f) - mu * mu;
        mz[tid] = make_float2(mu, rsqrtf(var + 1e-5f));
    }
    __syncthreads();

#pragma unroll
    for (int mt = 0; mt < 4; mt++) {
#pragma unroll
        for (int h = 0; h < 2; h++) {
            const int row = mt * 16 + h * 8 + g;
            const float2 m = mz[row];
#pragma unroll
            for (int nt = 0; nt < 8; nt++) {
                const int col = wid * 64 + nt * 8 + t4 * 2;
                const float2 gv = *(const float2*)(gamma + col);
                const float2 tv = *(const float2*)(beta + col);
                const float v0 = acc[mt][nt][h * 2 + 0];
                const float v1 = acc[mt][nt][h * 2 + 1];
                const float o0 = fmaxf((v0 - m.x) * m.y * gv.x + tv.x, 0.0f);
                const float o1 = fmaxf((v1 - m.x) * m.y * gv.y + tv.y, 0.0f);
                *(float2*)(out + (size_t)(m0 + row) * 512 + col) = make_float2(o0, o1);
            }
        }
    }
}

extern "C" void kernel_launch(void* const* d_in, const int* in_sizes, int n_in,
                              void* d_out, int out_size)
{
    // metadata order: embeddings, W_proj, b_proj, W_enc, b_enc, ln_gamma, ln_beta
    const float* emb   = (const float*)d_in[0];
    const float* W_enc = (const float*)d_in[3];
    const float* b_enc = (const float*)d_in[4];
    const float* gam   = (const float*)d_in[5];
    const float* bet   = (const float*)d_in[6];
    float* out = (float*)d_out;

    prep_a_kernel<<<16384 * 64 / 256, 256>>>(emb);
    prep_b_kernel<<<256 * 128 / 256, 256>>>(W_enc);

    cudaFuncSetAttribute(gemm_ln_kernel,
                         cudaFuncAttributeMaxDynamicSharedMemorySize, SMEM_TOTAL);
    gemm_ln_kernel<<<16384 / MTILE, THREADS, SMEM_TOTAL>>>(b_enc, gam, bet, out);
}

// round 6
// speedup vs baseline: 1.0948x; 1.0948x over previous
#include <cuda_runtime.h>
#include <cuda_bf16.h>
#include <cstdint>

// ============================================================================
// SimplifiedTopologyExtractor — algebraic reduction:
//   out = ReLU(LayerNorm(emb[:, :, :256] @ W_enc + b_enc))
// (pooled == embeddings exactly; proj/cdist/topk is dead code.)
//
// fp32 GEMM via bf16 hi/lo split on mma.sync m16n8k16:
//   a*b ≈ ah*bh + ah*bl + al*bh   (err ~2^-18 rel).
// Round 6: MTILE 64->32, __launch_bounds__(256,2) => 2 CTAs/SM (4 warps/SMSP)
// so one CTA's load/sync phases overlap the other's MMA phase. B prepped to
// bf16 once (halves L2 broadcast traffic); A converted in-loop (per-CTA data).
// ============================================================================

#define THREADS 256
#define MTILE 32
#define KD 256
#define KCH 16
#define NCHUNK (KD / KCH)

// smem strides/offsets (bytes)
#define A_STRIDE 48
#define B_STRIDE 1040
#define OFF_AH 0
#define OFF_AL (32 * A_STRIDE)                  // 1536
#define OFF_BH (2 * 32 * A_STRIDE)              // 3072
#define OFF_BL (OFF_BH + KCH * B_STRIDE)        // 19712
#define STAGE_B (OFF_BL + KCH * B_STRIDE)       // 36352 per stage
#define OFF_PS (2 * STAGE_B)                    // 72704
#define OFF_PQ (OFF_PS + 1024)
#define OFF_MZ (OFF_PQ + 1024)
#define SMEM_TOTAL (OFF_MZ + 256)               // 75008 -> 2 CTAs = 150 KB/SM

// prepped B (bf16 hi/lo), chunk-shaped: [chunk 16][part 2][kr 16][n 512]
__device__ __align__(16) unsigned char g_Bpre[16 * 32768];   // 512 KB

__device__ __forceinline__ uint32_t smem_u32(const void* p) {
    uint32_t a;
    asm("{ .reg .u64 t; cvta.to.shared.u64 t, %1; cvt.u32.u64 %0, t; }"
        : "=r"(a) : "l"(p));
    return a;
}

__device__ __forceinline__ void cp_async16(uint32_t dst, const void* src) {
    asm volatile("cp.async.cg.shared.global [%0], [%1], 16;\n"
                 :: "r"(dst), "l"(src));
}

__device__ __forceinline__ void ldsm4(uint32_t* r, uint32_t addr) {
    asm volatile("ldmatrix.sync.aligned.m8n8.x4.shared.b16 {%0,%1,%2,%3}, [%4];"
                 : "=r"(r[0]), "=r"(r[1]), "=r"(r[2]), "=r"(r[3]) : "r"(addr));
}
__device__ __forceinline__ void ldsm4t(uint32_t* r, uint32_t addr) {
    asm volatile("ldmatrix.sync.aligned.m8n8.x4.trans.shared.b16 {%0,%1,%2,%3}, [%4];"
                 : "=r"(r[0]), "=r"(r[1]), "=r"(r[2]), "=r"(r[3]) : "r"(addr));
}

__device__ __forceinline__ void mma16816(float* d, const uint32_t* a,
                                         uint32_t b0, uint32_t b1) {
    asm volatile(
        "mma.sync.aligned.m16n8k16.row.col.f32.bf16.bf16.f32 "
        "{%0,%1,%2,%3}, {%4,%5,%6,%7}, {%8,%9}, {%0,%1,%2,%3};"
        : "+f"(d[0]), "+f"(d[1]), "+f"(d[2]), "+f"(d[3])
        : "r"(a[0]), "r"(a[1]), "r"(a[2]), "r"(a[3]), "r"(b0), "r"(b1));
}

__device__ __forceinline__ void split_f4(float4 v, uint32_t& h01, uint32_t& h23,
                                         uint32_t& l01, uint32_t& l23) {
    float f[4] = {v.x, v.y, v.z, v.w};
    unsigned short hs[4], ls[4];
#pragma unroll
    for (int i = 0; i < 4; i++) {
        __nv_bfloat16 h = __float2bfloat16(f[i]);
        float rem = f[i] - __bfloat162float(h);
        __nv_bfloat16 l = __float2bfloat16(rem);
        hs[i] = __bfloat16_as_ushort(h);
        ls[i] = __bfloat16_as_ushort(l);
    }
    h01 = (uint32_t)hs[0] | ((uint32_t)hs[1] << 16);
    h23 = (uint32_t)hs[2] | ((uint32_t)hs[3] << 16);
    l01 = (uint32_t)ls[0] | ((uint32_t)ls[1] << 16);
    l23 = (uint32_t)ls[2] | ((uint32_t)ls[3] << 16);
}

// ---- prep B: W_enc[256,512] -> hi/lo bf16, chunk-tiled (1 MB traffic) ----
__global__ void prep_b_kernel(const float* __restrict__ W) {
    int t = blockIdx.x * 256 + threadIdx.x;   // 256 * 128
    int k  = t >> 7;
    int nq = t & 127;
    float4 v = *(const float4*)(W + (size_t)k * 512 + nq * 4);
    uint32_t h01, h23, l01, l23;
    split_f4(v, h01, h23, l01, l23);
    int c = k >> 4, kr = k & 15;
    size_t base = (size_t)c * 32768 + (size_t)kr * 1024 + nq * 8;
    *(uint2*)(g_Bpre + base)         = make_uint2(h01, h23);
    *(uint2*)(g_Bpre + base + 16384) = make_uint2(l01, l23);
}

// ---- GEMM + fused bias/LayerNorm/ReLU ----
__global__ void __launch_bounds__(THREADS, 2)
gemm_ln_kernel(const float* __restrict__ emb,
               const float* __restrict__ bias,
               const float* __restrict__ gamma,
               const float* __restrict__ beta,
               float* __restrict__ out)
{
    extern __shared__ __align__(1024) unsigned char smem[];
    const uint32_t sb = smem_u32(smem);
    const int tid = threadIdx.x;
    const int wid = tid >> 5;
    const int lane = tid & 31;
    const int m0 = blockIdx.x * MTILE;

    float acc[2][8][4];
#pragma unroll
    for (int mt = 0; mt < 2; mt++)
#pragma unroll
        for (int nt = 0; nt < 8; nt++)
#pragma unroll
            for (int e = 0; e < 4; e++) acc[mt][nt][e] = 0.0f;

    // A staging: each thread owns one float2 of the 32x16 chunk
    const int a_row = tid >> 3, a_kp = tid & 7;
    const float* a_src = emb + (size_t)(m0 + a_row) * 512 + a_kp * 2;
    const uint32_t a_off = (uint32_t)a_row * A_STRIDE + (uint32_t)a_kp * 4;

    // B staging: 8 x 16B per thread
    uint32_t b_dst_off[8];
#pragma unroll
    for (int i = 0; i < 8; i++) {
        int g = tid + i * 256;
        int part = g >> 10, kr = (g >> 6) & 15, col = g & 63;
        b_dst_off[i] = (uint32_t)(part ? OFF_BL : OFF_BH)
                     + (uint32_t)kr * B_STRIDE + (uint32_t)col * 16;
    }

#define ISSUE_B(cc) do {                                                        \
    const int _c = (cc);                                                        \
    const uint32_t _st = sb + (uint32_t)(_c & 1) * STAGE_B;                     \
    _Pragma("unroll")                                                           \
    for (int _i = 0; _i < 8; _i++)                                              \
        cp_async16(_st + b_dst_off[_i],                                         \
                   g_Bpre + (size_t)_c * 32768 + (size_t)(tid + _i * 256) * 16);\
    asm volatile("cp.async.commit_group;");                                     \
} while (0)

    // prologue
    ISSUE_B(0);
    float2 aS = *(const float2*)(a_src);

    // ldmatrix lane addressing
    const uint32_t lrow = lane & 15, lchk = lane >> 4;
    const uint32_t aLane = lrow * A_STRIDE + lchk * 16;
    const uint32_t bLane = lrow * B_STRIDE + lchk * 16 + (uint32_t)wid * 128;

#pragma unroll 1
    for (int c = 0; c < NCHUNK; ++c) {
        const uint32_t stOff = (uint32_t)(c & 1) * STAGE_B;

        // STS A chunk c (convert 2 values)
        {
            __nv_bfloat16 h0 = __float2bfloat16(aS.x);
            __nv_bfloat16 h1 = __float2bfloat16(aS.y);
            __nv_bfloat16 l0 = __float2bfloat16(aS.x - __bfloat162float(h0));
            __nv_bfloat16 l1 = __float2bfloat16(aS.y - __bfloat162float(h1));
            uint32_t h01 = (uint32_t)__bfloat16_as_ushort(h0)
                         | ((uint32_t)__bfloat16_as_ushort(h1) << 16);
            uint32_t l01 = (uint32_t)__bfloat16_as_ushort(l0)
                         | ((uint32_t)__bfloat16_as_ushort(l1) << 16);
            *(uint32_t*)(smem + stOff + OFF_AH + a_off) = h01;
            *(uint32_t*)(smem + stOff + OFF_AL + a_off) = l01;
        }
        if (c + 1 < NCHUNK) aS = *(const float2*)(a_src + (c + 1) * 16);

        asm volatile("cp.async.wait_group 0;");
        __syncthreads();   // chunk c fully staged; all warps done with MMA(c-1)

        if (c + 1 < NCHUNK) ISSUE_B(c + 1);   // writes stage (c+1)&1, safe now

        const uint32_t st = sb + stOff;
        uint32_t Ah[2][4], Al[2][4];
#pragma unroll
        for (int mt = 0; mt < 2; mt++) {
            ldsm4(Ah[mt], st + OFF_AH + (uint32_t)mt * 16 * A_STRIDE + aLane);
            ldsm4(Al[mt], st + OFF_AL + (uint32_t)mt * 16 * A_STRIDE + aLane);
        }
#pragma unroll
        for (int j = 0; j < 4; j++) {
            uint32_t Bh[4], Bl[4];
            ldsm4t(Bh, st + OFF_BH + (uint32_t)j * 32 + bLane);
            ldsm4t(Bl, st + OFF_BL + (uint32_t)j * 32 + bLane);
#pragma unroll
            for (int mt = 0; mt < 2; mt++) {
#pragma unroll
                for (int nn = 0; nn < 2; nn++) {
                    float* d = acc[mt][j * 2 + nn];
                    mma16816(d, Ah[mt], Bh[nn * 2], Bh[nn * 2 + 1]);
                    mma16816(d, Ah[mt], Bl[nn * 2], Bl[nn * 2 + 1]);
                    mma16816(d, Al[mt], Bh[nn * 2], Bh[nn * 2 + 1]);
                }
            }
        }
    }

    // ======== fused epilogue: +bias, LayerNorm(512), *gamma+beta, ReLU ========
    const int g = lane >> 2, t4 = lane & 3;
    float* ps = (float*)(smem + OFF_PS);      // [32 rows][8 warps]
    float* pq = (float*)(smem + OFF_PQ);
    float2* mz = (float2*)(smem + OFF_MZ);    // [32] {mu, rstd}

    float s[4], q[4];                          // row slots: mt*2 + h
#pragma unroll
    for (int r4 = 0; r4 < 4; r4++) { s[r4] = 0.f; q[r4] = 0.f; }

#pragma unroll
    for (int mt = 0; mt < 2; mt++) {
#pragma unroll
        for (int nt = 0; nt < 8; nt++) {
            const int col = wid * 64 + nt * 8 + t4 * 2;
            const float2 bv = *(const float2*)(bias + col);
            acc[mt][nt][0] += bv.x; acc[mt][nt][1] += bv.y;
            acc[mt][nt][2] += bv.x; acc[mt][nt][3] += bv.y;
            s[mt * 2 + 0] += acc[mt][nt][0] + acc[mt][nt][1];
            q[mt * 2 + 0] += acc[mt][nt][0] * acc[mt][nt][0]
                           + acc[mt][nt][1] * acc[mt][nt][1];
            s[mt * 2 + 1] += acc[mt][nt][2] + acc[mt][nt][3];
            q[mt * 2 + 1] += acc[mt][nt][2] * acc[mt][nt][2]
                           + acc[mt][nt][3] * acc[mt][nt][3];
        }
    }
#pragma unroll
    for (int r4 = 0; r4 < 4; r4++) {
        s[r4] += __shfl_xor_sync(0xffffffffu, s[r4], 1);
        q[r4] += __shfl_xor_sync(0xffffffffu, q[r4], 1);
        s[r4] += __shfl_xor_sync(0xffffffffu, s[r4], 2);
        q[r4] += __shfl_xor_sync(0xffffffffu, q[r4], 2);
    }
    if (t4 == 0) {
#pragma unroll
        for (int r4 = 0; r4 < 4; r4++) {
            const int row = (r4 >> 1) * 16 + (r4 & 1) * 8 + g;
            ps[row * 8 + wid] = s[r4];
            pq[row * 8 + wid] = q[r4];
        }
    }
    __syncthreads();
    if (tid < 32) {
        float ss = 0.f, qq = 0.f;
#pragma unroll
        for (int w = 0; w < 8; w++) { ss += ps[tid * 8 + w]; qq += pq[tid * 8 + w]; }
        const float mu  = ss * (1.0f / 512.0f);
        const float var = qq * (1.0f / 512.0f) - mu * mu;
        mz[tid] = make_float2(mu, rsqrtf(var + 1e-5f));
    }
    __syncthreads();

#pragma unroll
    for (int mt = 0; mt < 2; mt++) {
#pragma unroll
        for (int h = 0; h < 2; h++) {
            const int row = mt * 16 + h * 8 + g;
            const float2 m = mz[row];
#pragma unroll
            for (int nt = 0; nt < 8; nt++) {
                const int col = wid * 64 + nt * 8 + t4 * 2;
                const float2 gv = *(const float2*)(gamma + col);
                const float2 tv = *(const float2*)(beta + col);
                const float v0 = acc[mt][nt][h * 2 + 0];
                const float v1 = acc[mt][nt][h * 2 + 1];
                const float o0 = fmaxf((v0 - m.x) * m.y * gv.x + tv.x, 0.0f);
                const float o1 = fmaxf((v1 - m.x) * m.y * gv.y + tv.y, 0.0f);
                *(float2*)(out + (size_t)(m0 + row) * 512 + col) = make_float2(o0, o1);
            }
        }
    }
}

extern "C" void kernel_launch(void* const* d_in, const int* in_sizes, int n_in,
                              void* d_out, int out_size)
{
    // metadata order: embeddings, W_proj, b_proj, W_enc, b_enc, ln_gamma, ln_beta
    const float* emb   = (const float*)d_in[0];
    const float* W_enc = (const float*)d_in[3];
    const float* b_enc = (const float*)d_in[4];
    const float* gam   = (const float*)d_in[5];
    const float* bet   = (const float*)d_in[6];
    float* out = (float*)d_out;

    prep_b_kernel<<<128, 256>>>(W_enc);

    cudaFuncSetAttribute(gemm_ln_kernel,
                         cudaFuncAttributeMaxDynamicSharedMemorySize, SMEM_TOTAL);
    gemm_ln_kernel<<<16384 / MTILE, THREADS, SMEM_TOTAL>>>(emb, b_enc, gam, bet, out);
}